// round 16
// baseline (speedup 1.0000x reference)
#include <cuda_runtime.h>
#include <math_constants.h>

#define WSZ    8
#define P2     64
#define CH     128
#define W1G    32
#define NWPB   1024
#define BATCH  8
#define NWIN   (BATCH*NWPB)
#define HD     32
#define NH     4
#define SHIFT  4
#define PSTR   132
#define NTHR   512

__device__ __forceinline__ int swz4(int tok, int c4) { return tok * 32 + (c4 ^ (tok & 7)); }
__device__ __forceinline__ int swz(int tok, int ch) {
    return tok * 128 + ((((ch >> 2) ^ (tok & 7))) << 2) + (ch & 3);
}
// pre-split k: uint2 slots, [tok][chpair]
__device__ __forceinline__ int kupz(int tok, int p) { return tok * 64 + (p ^ ((tok & 3) << 2)); }
// pre-split v (transposed): uint2 slots, [ch][tokpair]
__device__ __forceinline__ int vupz(int ch, int tp) {
    return ch * 32 + (tp ^ (((ch & 3) << 2) | ((ch >> 2) & 3)));
}

// bf16 split helpers
__device__ __forceinline__ float trunc_hi(float x) {
    return __uint_as_float(__float_as_uint(x) & 0xffff0000u);
}
__device__ __forceinline__ unsigned prmt_hi(float a, float b) {
    unsigned r;
    asm("prmt.b32 %0, %1, %2, 0x7632;" : "=r"(r)
        : "r"(__float_as_uint(a)), "r"(__float_as_uint(b)));
    return r;
}
__device__ __forceinline__ unsigned pack_rn(float a, float b) {
    unsigned r;
    asm("cvt.rn.bf16x2.f32 %0, %1, %2;" : "=r"(r) : "f"(b), "f"(a));
    return r;
}
__device__ __forceinline__ void split2(float2 f, unsigned& h, unsigned& l) {
    h = prmt_hi(f.x, f.y);
    l = pack_rn(f.x - trunc_hi(f.x), f.y - trunc_hi(f.y));
}
__device__ __forceinline__ uint2 split_pair(float x, float y) {
    uint2 u;
    u.x = prmt_hi(x, y);
    u.y = pack_rn(x - trunc_hi(x), y - trunc_hi(y));
    return u;
}
__device__ __forceinline__ void mma_bf16(float c[4], unsigned a0, unsigned a1,
                                         unsigned a2, unsigned a3,
                                         unsigned b0, unsigned b1) {
    asm volatile(
        "mma.sync.aligned.m16n8k16.row.col.f32.bf16.bf16.f32 "
        "{%0,%1,%2,%3}, {%4,%5,%6,%7}, {%8,%9}, {%0,%1,%2,%3};\n"
        : "+f"(c[0]), "+f"(c[1]), "+f"(c[2]), "+f"(c[3])
        : "r"(a0), "r"(a1), "r"(a2), "r"(a3), "r"(b0), "r"(b1));
}
__device__ __forceinline__ void mma3u(float c[4], uint2 a0, uint2 a1, uint2 a2, uint2 a3,
                                      unsigned bh0, unsigned bh1, unsigned bl0, unsigned bl1) {
    mma_bf16(c, a0.x, a1.x, a2.x, a3.x, bh0, bh1);
    mma_bf16(c, a0.y, a1.y, a2.y, a3.y, bh0, bh1);
    mma_bf16(c, a0.x, a1.x, a2.x, a3.x, bl0, bl1);
}

// ---------------- scratch ----------------
__device__ float g_xw [(size_t)NWIN * P2 * CH];
__device__ float g_off[NWIN * P2 * 2];
__device__ float g_oi [NWIN * 2];
// merged weight fragments: uint4 {bh0, bh1, bl0, bl1}, idx = (n8*8+ks)*32 + lane
__device__ uint4 g_qf[4096], g_kf[4096], g_vf[4096], g_of[4096];
// expanded rel-pos bias: [head][i][j], 64KB, L2-resident
__device__ float g_biasT[NH * 64 * 64];

// ---------------- kernel 0: weight fragment + bias table prep ----------------
__global__ __launch_bounds__(256)
void k_wfrag(const float* __restrict__ q_w, const float* __restrict__ kv_w,
             const float* __restrict__ o_w, const float* __restrict__ rpp)
{
    const int i = blockIdx.x * 256 + threadIdx.x;
    const int lane = i & 31, ks = (i >> 5) & 7, n8 = i >> 8;
    const int n  = n8 * 8 + (lane >> 2);
    const int kb = ks * 16 + (lane & 3) * 2;

    #define DO_FRAG(w, S, O, f) {                                             \
        const float v00 = w[(size_t)(kb    ) * S + O + n];                    \
        const float v01 = w[(size_t)(kb + 1) * S + O + n];                    \
        const float v10 = w[(size_t)(kb + 8) * S + O + n];                    \
        const float v11 = w[(size_t)(kb + 9) * S + O + n];                    \
        f[i] = make_uint4(prmt_hi(v00, v01), prmt_hi(v10, v11),               \
                          pack_rn(v00 - trunc_hi(v00), v01 - trunc_hi(v01)),  \
                          pack_rn(v10 - trunc_hi(v10), v11 - trunc_hi(v11))); \
    }
    DO_FRAG(q_w, 128, 0,   g_qf)
    DO_FRAG(kv_w, 256, 0,   g_kf)
    DO_FRAG(kv_w, 256, 128, g_vf)
    DO_FRAG(o_w, 128, 0,   g_of)
    #undef DO_FRAG

    // bias table: 16384 entries, 4 per thread
    #pragma unroll
    for (int t = 0; t < 4; ++t) {
        const int e  = i * 4 + t;
        const int hh = e >> 12, rest = e & 4095;
        const int bi = rest >> 6, bj = rest & 63;
        const int pi_i = bi >> 3, pj_i = bi & 7;
        const int pi_j = bj >> 3, pj_j = bj & 7;
        g_biasT[e] = rpp[hh * 225 + (pi_i - pi_j + 7) * 15 + (pj_i - pj_j + 7)];
    }
}

// ---------------- kernel 1: window gather + offset MLPs ----------------
__global__ __launch_bounds__(256)
void k_prep(const float* __restrict__ x,
            const float* __restrict__ wi_w, const float* __restrict__ wi_b,
            const float* __restrict__ w1_w, const float* __restrict__ w1_b,
            const float* __restrict__ w2_w, const float* __restrict__ w2_b)
{
    __shared__ float sT[P2 * PSTR];
    __shared__ float sT1[P2 * 2];

    const int win = blockIdx.x;
    const int b   = win >> 10;
    const int wr  = win & 1023;
    const int wi  = wr >> 5;
    const int wj  = wr & 31;
    const int tid = threadIdx.x;

    float4* gx4 = (float4*)(g_xw + (size_t)win * P2 * CH);

    for (int i4 = tid; i4 < P2 * CH / 4; i4 += 256) {
        const int tok = i4 >> 5, c4 = i4 & 31;
        const int pi = tok >> 3, pj = tok & 7;
        const int r = (wi * 8 + pi + SHIFT) & 255;
        const int c = (wj * 8 + pj + SHIFT) & 255;
        const float4 v = *(const float4*)(x + (size_t)((((b << 8) + r) << 8) + c) * CH + c4 * 4);
        *(float4*)(sT + tok * PSTR + c4 * 4) = v;
        gx4[i4] = v;
    }
    __syncthreads();

    {
        const int kind = tid >> 7;
        const int rem  = tid & 127;
        const int tok  = rem >> 1;
        const int d    = rem & 1;
        const float* w = kind ? w1_w : wi_w;
        float acc = 0.f;
        #pragma unroll 8
        for (int ch = 0; ch < 128; ++ch)
            acc = fmaf(sT[tok * PSTR + ch], w[ch * 2 + d], acc);
        if (kind) sT1[tok * 2 + d] = acc + w1_b[d];
        else      g_off[win * 128 + tok * 2 + d] = acc + wi_b[d];
    }
    __syncthreads();

    if (tid < 2) {
        float acc = w2_b[tid];
        for (int f = 0; f < 128; ++f)
            acc = fmaf(sT1[f], w2_w[f * 2 + tid], acc);
        g_oi[win * 2 + tid] = acc;
    }
}

// ---- bf16x3 MMA mainloops for GEMMs (warp = rg x cg of 16x32 tile) ----
#define MMA_KSTEP(LD0, LD1, LD2, LD3)                                          \
    unsigned ah0, al0, ah1, al1, ah2, al2, ah3, al3;                           \
    split2(LD0, ah0, al0); split2(LD1, ah1, al1);                              \
    split2(LD2, ah2, al2); split2(LD3, ah3, al3);                              \
    _Pragma("unroll")                                                          \
    for (int nt = 0; nt < 4; ++nt) {                                           \
        const uint4 bf = __ldg(wf + ((cg * 4 + nt) * 8 + ks) * 32 + lane);     \
        mma_bf16(c[nt], ah0, ah1, ah2, ah3, bf.x, bf.y);                       \
        mma_bf16(c[nt], al0, al1, al2, al3, bf.x, bf.y);                       \
        mma_bf16(c[nt], ah0, ah1, ah2, ah3, bf.z, bf.w);                       \
    }

__device__ __forceinline__
void mma_main_smem(const float* __restrict__ A, const uint4* __restrict__ wf,
                   int wp, int lane, float c[4][4])
{
    const int rg = wp >> 2, cg = wp & 3;
    const int r = rg * 16 + (lane >> 2);
    const int q2 = (lane & 3) * 2;
    #pragma unroll
    for (int ks = 0; ks < 8; ++ks) {
        const int k0 = ks * 16;
        MMA_KSTEP(*(const float2*)(A + swz(r,     k0 + q2)),
                  *(const float2*)(A + swz(r + 8, k0 + q2)),
                  *(const float2*)(A + swz(r,     k0 + 8 + q2)),
                  *(const float2*)(A + swz(r + 8, k0 + 8 + q2)))
    }
}

__device__ __forceinline__
void mma_main_gmem(const float* __restrict__ A, const uint4* __restrict__ wf,
                   int wp, int lane, float c[4][4])
{
    const int rg = wp >> 2, cg = wp & 3;
    const int r = rg * 16 + (lane >> 2);
    const int q2 = (lane & 3) * 2;
    #pragma unroll
    for (int ks = 0; ks < 8; ++ks) {
        const int k0 = ks * 16;
        MMA_KSTEP(__ldg((const float2*)(A + (r    ) * CH + k0 + q2)),
                  __ldg((const float2*)(A + (r + 8) * CH + k0 + q2)),
                  __ldg((const float2*)(A + (r    ) * CH + k0 + 8 + q2)),
                  __ldg((const float2*)(A + (r + 8) * CH + k0 + 8 + q2)))
    }
}

// epilogue -> f32 swz buffer
__device__ __forceinline__
void mma_epi_smem(float c[4][4], const float* __restrict__ bias, int boff,
                  float* __restrict__ out_s, int wp, int lane)
{
    const int rg = wp >> 2, cg = wp & 3;
    const int r = rg * 16 + (lane >> 2);
    const int q2 = (lane & 3) * 2;
    #pragma unroll
    for (int nt = 0; nt < 4; ++nt) {
        const int col = cg * 32 + nt * 8 + q2;
        const float2 bv = *(const float2*)(bias + boff + col);
        *(float2*)(out_s + swz(r,     col)) = make_float2(c[nt][0] + bv.x, c[nt][1] + bv.y);
        *(float2*)(out_s + swz(r + 8, col)) = make_float2(c[nt][2] + bv.x, c[nt][3] + bv.y);
    }
}

// epilogue -> pre-split kU (uint2, kupz layout)
__device__ __forceinline__
void mma_epi_kU(float c[4][4], const float* __restrict__ bias,
                uint2* __restrict__ outU, int wp, int lane)
{
    const int rg = wp >> 2, cg = wp & 3;
    const int r = rg * 16 + (lane >> 2);
    const int q2 = (lane & 3) * 2;
    #pragma unroll
    for (int nt = 0; nt < 4; ++nt) {
        const int col = cg * 32 + nt * 8 + q2;
        const float2 bv = *(const float2*)(bias + col);
        outU[kupz(r,     col >> 1)] = split_pair(c[nt][0] + bv.x, c[nt][1] + bv.y);
        outU[kupz(r + 8, col >> 1)] = split_pair(c[nt][2] + bv.x, c[nt][3] + bv.y);
    }
}

// ---------------- kernel 2 ----------------
__global__ __launch_bounds__(NTHR, 2)
void k_main(const float* __restrict__ q_b, const float* __restrict__ kv_b,
            const float* __restrict__ o_b, float* __restrict__ out)
{
    extern __shared__ float sm[];
    float* bufA = sm;            // q -> attn-out (in-place per warp region)
    float* bufB = bufA + 8192;   // xd2 -> v f32 -> vU uint2 (transposed, pre-split)
    float* bufC = bufB + 8192;   // xd -> kU (pre-split uint2)

    const int win = blockIdx.x;
    const int b   = win >> 10;
    const int wr  = win & 1023;
    const int wi  = wr >> 5;
    const int wj  = wr & 31;
    const int tid = threadIdx.x;
    const int wp  = tid >> 5, tx = tid & 31;

    // ---- inter-window bilinear blend -> bufC (xd) ----
    {
        const float ox = __ldg(g_oi + win * 2 + 0), oy = __ldg(g_oi + win * 2 + 1);
        const float gxp = (float)wj + ox, gyp = (float)wi + oy;
        const float x0f = floorf(gxp), y0f = floorf(gyp);
        const float fx = gxp - x0f, fy = gyp - y0f;
        const int x0 = (int)x0f, y0 = (int)y0f;
        const float wgt[4] = {(1.f - fx) * (1.f - fy), fx * (1.f - fy),
                              (1.f - fx) * fy,          fx * fy};
        const float4* nb[4];
        float nww[4];
        #pragma unroll
        for (int k = 0; k < 4; ++k) {
            const int xx = x0 + (k & 1), yy = y0 + (k >> 1);
            const bool valid = (xx >= 0) && (xx < W1G) && (yy >= 0) && (yy < W1G);
            nb[k]  = (const float4*)(valid ? (g_xw + (size_t)((b << 10) + (yy << 5) + xx) * P2 * CH)
                                           : g_xw);
            nww[k] = valid ? wgt[k] : 0.f;
        }
        float4* outv4 = (float4*)bufC;
        for (int i4 = tid; i4 < 2048; i4 += NTHR) {
            const float4 v0 = __ldg(nb[0] + i4), v1 = __ldg(nb[1] + i4);
            const float4 v2 = __ldg(nb[2] + i4), v3 = __ldg(nb[3] + i4);
            float4 r;
            r.x = nww[0]*v0.x + nww[1]*v1.x + nww[2]*v2.x + nww[3]*v3.x;
            r.y = nww[0]*v0.y + nww[1]*v1.y + nww[2]*v2.y + nww[3]*v3.y;
            r.z = nww[0]*v0.z + nww[1]*v1.z + nww[2]*v2.z + nww[3]*v3.z;
            r.w = nww[0]*v0.w + nww[1]*v1.w + nww[2]*v2.w + nww[3]*v3.w;
            outv4[swz4(i4 >> 5, i4 & 31)] = r;
        }
    }
    __syncthreads();

    // ---- intra-window gather bufC -> bufB (xd2) ----
    {
        const float4* inv4 = (const float4*)bufC;
        float4* outv4 = (float4*)bufB;
        #pragma unroll
        for (int it = 0; it < 4; ++it) {
            const int i4 = tid + it * NTHR;
            const int tok = i4 >> 5, c4 = i4 & 31;
            const int pi = tok >> 3, pj = tok & 7;
            const float o0 = __ldg(g_off + win * 128 + tok * 2);
            const float o1 = __ldg(g_off + win * 128 + tok * 2 + 1);
            const float gx2 = (float)pj + o0, gy2 = (float)pi + o1;
            const float xf = floorf(gx2), yf = floorf(gy2);
            const float fx = gx2 - xf, fy = gy2 - yf;
            const int x0 = (int)xf, y0 = (int)yf;
            const float ww[4] = {(1.f - fx) * (1.f - fy), fx * (1.f - fy),
                                 (1.f - fx) * fy,          fx * fy};
            float4 r = make_float4(0.f, 0.f, 0.f, 0.f);
            #pragma unroll
            for (int k = 0; k < 4; ++k) {
                const int xx = x0 + (k & 1), yy = y0 + (k >> 1);
                const bool valid = (xx >= 0) && (xx < WSZ) && (yy >= 0) && (yy < WSZ);
                const int idx = valid ? (yy * 8 + xx) : 0;
                const float wk = valid ? ww[k] : 0.f;
                const float4 a = inv4[swz4(idx, c4)];
                r.x = fmaf(wk, a.x, r.x);
                r.y = fmaf(wk, a.y, r.y);
                r.z = fmaf(wk, a.z, r.z);
                r.w = fmaf(wk, a.w, r.w);
            }
            outv4[swz4(tok, c4)] = r;
        }
    }
    __syncthreads();

    // ---- GEMMs on tensor cores ----
    {   // k: bufB(xd2) -> kU in bufC (xd dead), PRE-SPLIT epilogue
        float c[4][4] = {};
        mma_main_smem(bufB, g_kf, wp, tx, c);
        mma_epi_kU(c, kv_b, (uint2*)bufC, wp, tx);
    }
    {   // q: gmem xw -> bufA
        float c[4][4] = {};
        mma_main_gmem(g_xw + (size_t)win * P2 * CH, g_qf, wp, tx, c);
        mma_epi_smem(c, q_b, 0, bufA, wp, tx);
    }
    {   // v: bufB -> bufB f32 in-place (barrier between reads and writes)
        float c[4][4] = {};
        mma_main_smem(bufB, g_vf, wp, tx, c);
        __syncthreads();
        mma_epi_smem(c, kv_b, 128, bufB, wp, tx);
    }
    __syncthreads();

    // ---- v transpose-split: bufB f32 [tok][ch] -> vU uint2 [ch][tokpair], in-place ----
    {
        uint2 hold[8];
        #pragma unroll
        for (int it = 0; it < 8; ++it) {
            const int idx = tid + it * NTHR;     // 0..4095
            const int tp = idx >> 7, ch = idx & 127;
            hold[it] = split_pair(bufB[swz(2 * tp, ch)], bufB[swz(2 * tp + 1, ch)]);
        }
        __syncthreads();
        uint2* vU = (uint2*)bufB;
        #pragma unroll
        for (int it = 0; it < 8; ++it) {
            const int idx = tid + it * NTHR;
            const int tp = idx >> 7, ch = idx & 127;
            vU[vupz(ch, tp)] = hold[it];
        }
    }
    __syncthreads();

    // ---- attention, register-resident per warp (hh = wp&3, rg = wp>>2) ----
    {
        const float scale = 0.17677669529663687f;
        const bool edge = (wi == W1G - 1) || (wj == W1G - 1);
        const int hh = wp & 3, rg = wp >> 2;
        const int rA = rg * 16 + (tx >> 2);
        const int q2 = (tx & 3) * 2;
        const int la3 = tx & 3;
        const uint2* kU = (const uint2*)bufC;
        const uint2* vU = (const uint2*)bufB;

        // -- QK --
        float c[8][4] = {};
        #pragma unroll
        for (int ks = 0; ks < 2; ++ks) {
            const int ch0 = hh * HD + ks * 16;
            unsigned ah0, al0, ah1, al1, ah2, al2, ah3, al3;
            split2(*(const float2*)(bufA + swz(rA,     ch0 + q2)),     ah0, al0);
            split2(*(const float2*)(bufA + swz(rA + 8, ch0 + q2)),     ah1, al1);
            split2(*(const float2*)(bufA + swz(rA,     ch0 + 8 + q2)), ah2, al2);
            split2(*(const float2*)(bufA + swz(rA + 8, ch0 + 8 + q2)), ah3, al3);
            const int chp = hh * 16 + ks * 8 + la3;
            #pragma unroll
            for (int nt = 0; nt < 8; ++nt) {
                const int n = nt * 8 + (tx >> 2);
                const uint2 b0 = kU[kupz(n, chp)];
                const uint2 b1 = kU[kupz(n, chp + 4)];
                mma_bf16(c[nt], ah0, ah1, ah2, ah3, b0.x, b1.x);
                mma_bf16(c[nt], al0, al1, al2, al3, b0.x, b1.x);
                mma_bf16(c[nt], ah0, ah1, ah2, ah3, b0.y, b1.y);
            }
        }

        // -- scale + bias (table) --
        const float* bT = g_biasT + hh * 4096;
        #pragma unroll
        for (int nt = 0; nt < 8; ++nt) {
            #pragma unroll
            for (int h2 = 0; h2 < 2; ++h2) {
                const int i = rA + 8 * h2;
                const float2 bb = __ldg((const float2*)(bT + i * 64 + nt * 8 + q2));
                c[nt][2 * h2 + 0] = fmaf(c[nt][2 * h2 + 0], scale, bb.x);
                c[nt][2 * h2 + 1] = fmaf(c[nt][2 * h2 + 1], scale, bb.y);
            }
        }
        // -- mask (edge windows only) --
        if (edge) {
            const bool lastRow = (wi == W1G - 1), lastCol = (wj == W1G - 1);
            #pragma unroll
            for (int nt = 0; nt < 8; ++nt) {
                #pragma unroll
                for (int h2 = 0; h2 < 2; ++h2) {
                    const int i = rA + 8 * h2;
                    const int pi_i = i >> 3, pj_i = i & 7;
                    #pragma unroll
                    for (int u = 0; u < 2; ++u) {
                        const int j = nt * 8 + q2 + u;
                        const int pi_j = j >> 3, pj_j = j & 7;
                        const bool msk = (lastRow && ((pi_i < 4) != (pi_j < 4)))
                                      || (lastCol && ((pj_i < 4) != (pj_j < 4)));
                        if (msk) c[nt][2 * h2 + u] = -CUDART_INF_F;
                    }
                }
            }
        }

        // -- softmax in registers --
        float m0 = -CUDART_INF_F, m1 = -CUDART_INF_F;
        #pragma unroll
        for (int nt = 0; nt < 8; ++nt) {
            m0 = fmaxf(m0, fmaxf(c[nt][0], c[nt][1]));
            m1 = fmaxf(m1, fmaxf(c[nt][2], c[nt][3]));
        }
        m0 = fmaxf(m0, __shfl_xor_sync(0xffffffffu, m0, 1));
        m0 = fmaxf(m0, __shfl_xor_sync(0xffffffffu, m0, 2));
        m1 = fmaxf(m1, __shfl_xor_sync(0xffffffffu, m1, 1));
        m1 = fmaxf(m1, __shfl_xor_sync(0xffffffffu, m1, 2));
        float s0 = 0.f, s1 = 0.f;
        #pragma unroll
        for (int nt = 0; nt < 8; ++nt) {
            c[nt][0] = __expf(c[nt][0] - m0);
            c[nt][1] = __expf(c[nt][1] - m0);
            c[nt][2] = __expf(c[nt][2] - m1);
            c[nt][3] = __expf(c[nt][3] - m1);
            s0 += c[nt][0] + c[nt][1];
            s1 += c[nt][2] + c[nt][3];
        }
        s0 += __shfl_xor_sync(0xffffffffu, s0, 1);
        s0 += __shfl_xor_sync(0xffffffffu, s0, 2);
        s1 += __shfl_xor_sync(0xffffffffu, s1, 1);
        s1 += __shfl_xor_sync(0xffffffffu, s1, 2);
        const float inv0 = 1.f / s0, inv1 = 1.f / s1;

        // -- pack probs -> PV A-fragments (C->A layout identity) --
        uint2 aF[4][4];
        #pragma unroll
        for (int ks = 0; ks < 4; ++ks) {
            aF[ks][0] = split_pair(c[2*ks][0]   * inv0, c[2*ks][1]   * inv0);
            aF[ks][1] = split_pair(c[2*ks][2]   * inv1, c[2*ks][3]   * inv1);
            aF[ks][2] = split_pair(c[2*ks+1][0] * inv0, c[2*ks+1][1] * inv0);
            aF[ks][3] = split_pair(c[2*ks+1][2] * inv1, c[2*ks+1][3] * inv1);
        }

        // -- PV: pre-split v loads, write in-place into bufA --
        #pragma unroll
        for (int nt = 0; nt < 4; ++nt) {
            float c4[4] = {};
            const int nV = hh * HD + nt * 8 + (tx >> 2);
            #pragma unroll
            for (int ks = 0; ks < 4; ++ks) {
                const uint2 b0 = vU[vupz(nV, ks * 8 + la3)];
                const uint2 b1 = vU[vupz(nV, ks * 8 + la3 + 4)];
                mma3u(c4, aF[ks][0], aF[ks][1], aF[ks][2], aF[ks][3],
                      b0.x, b1.x, b0.y, b1.y);
            }
            const int colO = hh * HD + nt * 8 + q2;
            *(float2*)(bufA + swz(rA,     colO)) = make_float2(c4[0], c4[1]);
            *(float2*)(bufA + swz(rA + 8, colO)) = make_float2(c4[2], c4[3]);
        }
    }
    __syncthreads();

    // ---- o projection on tensor cores + un-shift scatter ----
    {
        float c[4][4] = {};
        mma_main_smem(bufA, g_of, wp, tx, c);
        const int rg = wp >> 2, cg = wp & 3;
        const int rA = rg * 16 + (tx >> 2);
        const int q2 = (tx & 3) * 2;
        #pragma unroll
        for (int nt = 0; nt < 4; ++nt) {
            const int col = cg * 32 + nt * 8 + q2;
            const float2 bv = *(const float2*)(o_b + col);
            #pragma unroll
            for (int h = 0; h < 2; ++h) {
                const int tok = rA + 8 * h;
                const int pi = tok >> 3, pj = tok & 7;
                const int rr = (wi * 8 + pi + SHIFT) & 255;
                const int cc = (wj * 8 + pj + SHIFT) & 255;
                float2 o;
                o.x = c[nt][2 * h + 0] + bv.x;
                o.y = c[nt][2 * h + 1] + bv.y;
                *(float2*)(out + (size_t)((((b << 8) + rr) << 8) + cc) * CH + col) = o;
            }
        }
    }
}

extern "C" void kernel_launch(void* const* d_in, const int* in_sizes, int n_in,
                              void* d_out, int out_size)
{
    const float* x    = (const float*)d_in[0];
    const float* rpp  = (const float*)d_in[1];
    const float* wi_w = (const float*)d_in[2];
    const float* wi_b = (const float*)d_in[3];
    const float* w1_w = (const float*)d_in[4];
    const float* w1_b = (const float*)d_in[5];
    const float* w2_w = (const float*)d_in[6];
    const float* w2_b = (const float*)d_in[7];
    const float* q_w  = (const float*)d_in[8];
    const float* q_b  = (const float*)d_in[9];
    const float* kv_w = (const float*)d_in[10];
    const float* kv_b = (const float*)d_in[11];
    const float* o_w  = (const float*)d_in[12];
    const float* o_b  = (const float*)d_in[13];
    float* out = (float*)d_out;

    const size_t smem2 = (size_t)(3 * 8192) * sizeof(float);   // 96 KB -> 2 CTAs/SM
    cudaFuncSetAttribute(k_main, cudaFuncAttributeMaxDynamicSharedMemorySize, (int)smem2);

    k_wfrag<<<16, 256>>>(q_w, kv_w, o_w, rpp);
    k_prep<<<NWIN, 256>>>(x, wi_w, wi_b, w1_w, w1_b, w2_w, w2_b);
    k_main<<<NWIN, NTHR, smem2>>>(q_b, kv_b, o_b, out);
}

// round 17
// speedup vs baseline: 1.0854x; 1.0854x over previous
#include <cuda_runtime.h>
#include <math_constants.h>

#define WSZ    8
#define P2     64
#define CH     128
#define W1G    32
#define NWPB   1024
#define BATCH  8
#define NWIN   (BATCH*NWPB)
#define HD     32
#define NH     4
#define SHIFT  4
#define PSTR   132
#define NTHR   512

__device__ __forceinline__ int swz4(int tok, int c4) { return tok * 32 + (c4 ^ (tok & 7)); }
__device__ __forceinline__ int swz(int tok, int ch) {
    return tok * 128 + ((((ch >> 2) ^ (tok & 7))) << 2) + (ch & 3);
}
// pre-split uint2 buffers: [tok][chpair p], conflict-free for frag loads + uint4 stores
__device__ __forceinline__ int kupz(int tok, int p) { return tok * 64 + (p ^ ((tok & 3) << 2)); }

// bf16 split helpers
__device__ __forceinline__ float trunc_hi(float x) {
    return __uint_as_float(__float_as_uint(x) & 0xffff0000u);
}
__device__ __forceinline__ unsigned prmt_hi(float a, float b) {
    unsigned r;
    asm("prmt.b32 %0, %1, %2, 0x7632;" : "=r"(r)
        : "r"(__float_as_uint(a)), "r"(__float_as_uint(b)));
    return r;
}
__device__ __forceinline__ unsigned pack_rn(float a, float b) {
    unsigned r;
    asm("cvt.rn.bf16x2.f32 %0, %1, %2;" : "=r"(r) : "f"(b), "f"(a));
    return r;
}
__device__ __forceinline__ uint2 split_pair(float x, float y) {
    uint2 u;
    u.x = prmt_hi(x, y);
    u.y = pack_rn(x - trunc_hi(x), y - trunc_hi(y));
    return u;
}
__device__ __forceinline__ void mma_bf16(float c[4], unsigned a0, unsigned a1,
                                         unsigned a2, unsigned a3,
                                         unsigned b0, unsigned b1) {
    asm volatile(
        "mma.sync.aligned.m16n8k16.row.col.f32.bf16.bf16.f32 "
        "{%0,%1,%2,%3}, {%4,%5,%6,%7}, {%8,%9}, {%0,%1,%2,%3};\n"
        : "+f"(c[0]), "+f"(c[1]), "+f"(c[2]), "+f"(c[3])
        : "r"(a0), "r"(a1), "r"(a2), "r"(a3), "r"(b0), "r"(b1));
}
// bf16x3: Ah*Bh + Al*Bh + Ah*Bl
__device__ __forceinline__ void mma3u(float c[4], uint2 a0, uint2 a1, uint2 a2, uint2 a3,
                                      unsigned bh0, unsigned bh1, unsigned bl0, unsigned bl1) {
    mma_bf16(c, a0.x, a1.x, a2.x, a3.x, bh0, bh1);
    mma_bf16(c, a0.y, a1.y, a2.y, a3.y, bh0, bh1);
    mma_bf16(c, a0.x, a1.x, a2.x, a3.x, bl0, bl1);
}

// ---------------- scratch ----------------
__device__ float g_xw [(size_t)NWIN * P2 * CH];
__device__ uint2 g_xq [(size_t)NWIN * P2 * 64];   // pre-split xw (q-GEMM A operand)
__device__ float g_off[NWIN * P2 * 2];
__device__ float g_oi [NWIN * 2];
// merged weight fragments: uint4 {bh0, bh1, bl0, bl1}, idx = (n8*8+ks)*32 + lane
__device__ uint4 g_qf[4096], g_kf[4096], g_vf[4096], g_of[4096];

// ---------------- kernel 0: weight fragment prep ----------------
__global__ __launch_bounds__(256)
void k_wfrag(const float* __restrict__ q_w, const float* __restrict__ kv_w,
             const float* __restrict__ o_w)
{
    const int i = blockIdx.x * 256 + threadIdx.x;
    const int lane = i & 31, ks = (i >> 5) & 7, n8 = i >> 8;
    const int n  = n8 * 8 + (lane >> 2);
    const int kb = ks * 16 + (lane & 3) * 2;

    #define DO_FRAG(w, S, O, f) {                                             \
        const float v00 = w[(size_t)(kb    ) * S + O + n];                    \
        const float v01 = w[(size_t)(kb + 1) * S + O + n];                    \
        const float v10 = w[(size_t)(kb + 8) * S + O + n];                    \
        const float v11 = w[(size_t)(kb + 9) * S + O + n];                    \
        f[i] = make_uint4(prmt_hi(v00, v01), prmt_hi(v10, v11),               \
                          pack_rn(v00 - trunc_hi(v00), v01 - trunc_hi(v01)),  \
                          pack_rn(v10 - trunc_hi(v10), v11 - trunc_hi(v11))); \
    }
    DO_FRAG(q_w, 128, 0,   g_qf)
    DO_FRAG(kv_w, 256, 0,   g_kf)
    DO_FRAG(kv_w, 256, 128, g_vf)
    DO_FRAG(o_w, 128, 0,   g_of)
    #undef DO_FRAG
}

// ---------------- kernel 1: window gather + offset MLPs + pre-split xw ----------------
__global__ __launch_bounds__(256)
void k_prep(const float* __restrict__ x,
            const float* __restrict__ wi_w, const float* __restrict__ wi_b,
            const float* __restrict__ w1_w, const float* __restrict__ w1_b,
            const float* __restrict__ w2_w, const float* __restrict__ w2_b)
{
    __shared__ float sT[P2 * PSTR];
    __shared__ float sT1[P2 * 2];

    const int win = blockIdx.x;
    const int b   = win >> 10;
    const int wr  = win & 1023;
    const int wi  = wr >> 5;
    const int wj  = wr & 31;
    const int tid = threadIdx.x;

    float4* gx4 = (float4*)(g_xw + (size_t)win * P2 * CH);

    for (int i4 = tid; i4 < P2 * CH / 4; i4 += 256) {
        const int tok = i4 >> 5, c4 = i4 & 31;
        const int pi = tok >> 3, pj = tok & 7;
        const int r = (wi * 8 + pi + SHIFT) & 255;
        const int c = (wj * 8 + pj + SHIFT) & 255;
        const float4 v = *(const float4*)(x + (size_t)((((b << 8) + r) << 8) + c) * CH + c4 * 4);
        *(float4*)(sT + tok * PSTR + c4 * 4) = v;
        gx4[i4] = v;
    }
    __syncthreads();

    // pre-split xw for q-GEMM / QK: g_xq[win][tok][p]
    {
        uint2* dst = g_xq + (size_t)win * P2 * 64;
        for (int i = tid; i < P2 * 64; i += 256) {
            const int tok = i >> 6, p = i & 63;
            dst[i] = split_pair(sT[tok * PSTR + 2 * p], sT[tok * PSTR + 2 * p + 1]);
        }
    }

    {
        const int kind = tid >> 7;
        const int rem  = tid & 127;
        const int tok  = rem >> 1;
        const int d    = rem & 1;
        const float* w = kind ? w1_w : wi_w;
        float acc = 0.f;
        #pragma unroll 8
        for (int ch = 0; ch < 128; ++ch)
            acc = fmaf(sT[tok * PSTR + ch], w[ch * 2 + d], acc);
        if (kind) sT1[tok * 2 + d] = acc + w1_b[d];
        else      g_off[win * 128 + tok * 2 + d] = acc + wi_b[d];
    }
    __syncthreads();

    if (tid < 2) {
        float acc = w2_b[tid];
        for (int f = 0; f < 128; ++f)
            acc = fmaf(sT1[f], w2_w[f * 2 + tid], acc);
        g_oi[win * 2 + tid] = acc;
    }
}

// ---- GEMM mainloop, A = pre-split smem uint2 (kupz layout); pure load+MMA ----
__device__ __forceinline__
void mma_main_pre(const uint2* __restrict__ A, const uint4* __restrict__ wf,
                  int wp, int lane, float c[4][4])
{
    const int rg = wp >> 2, cg = wp & 3;
    const int r = rg * 16 + (lane >> 2);
    const int la3 = lane & 3;
    #pragma unroll
    for (int ks = 0; ks < 8; ++ks) {
        const uint2 a0 = A[kupz(r,     ks * 8 + la3)];
        const uint2 a1 = A[kupz(r + 8, ks * 8 + la3)];
        const uint2 a2 = A[kupz(r,     ks * 8 + 4 + la3)];
        const uint2 a3 = A[kupz(r + 8, ks * 8 + 4 + la3)];
        #pragma unroll
        for (int nt = 0; nt < 4; ++nt) {
            const uint4 bf = __ldg(wf + ((cg * 4 + nt) * 8 + ks) * 32 + lane);
            mma3u(c[nt], a0, a1, a2, a3, bf.x, bf.y, bf.z, bf.w);
        }
    }
}

// same, A from gmem (linear [tok][p])
__device__ __forceinline__
void mma_main_preg(const uint2* __restrict__ A, const uint4* __restrict__ wf,
                   int wp, int lane, float c[4][4])
{
    const int rg = wp >> 2, cg = wp & 3;
    const int r = rg * 16 + (lane >> 2);
    const int la3 = lane & 3;
    #pragma unroll
    for (int ks = 0; ks < 8; ++ks) {
        const uint2 a0 = __ldg(A + (r    ) * 64 + ks * 8 + la3);
        const uint2 a1 = __ldg(A + (r + 8) * 64 + ks * 8 + la3);
        const uint2 a2 = __ldg(A + (r    ) * 64 + ks * 8 + 4 + la3);
        const uint2 a3 = __ldg(A + (r + 8) * 64 + ks * 8 + 4 + la3);
        #pragma unroll
        for (int nt = 0; nt < 4; ++nt) {
            const uint4 bf = __ldg(wf + ((cg * 4 + nt) * 8 + ks) * 32 + lane);
            mma3u(c[nt], a0, a1, a2, a3, bf.x, bf.y, bf.z, bf.w);
        }
    }
}

// epilogue -> f32 swz buffer (v)
__device__ __forceinline__
void mma_epi_smem(float c[4][4], const float* __restrict__ bias, int boff,
                  float* __restrict__ out_s, int wp, int lane)
{
    const int rg = wp >> 2, cg = wp & 3;
    const int r = rg * 16 + (lane >> 2);
    const int q2 = (lane & 3) * 2;
    #pragma unroll
    for (int nt = 0; nt < 4; ++nt) {
        const int col = cg * 32 + nt * 8 + q2;
        const float2 bv = *(const float2*)(bias + boff + col);
        *(float2*)(out_s + swz(r,     col)) = make_float2(c[nt][0] + bv.x, c[nt][1] + bv.y);
        *(float2*)(out_s + swz(r + 8, col)) = make_float2(c[nt][2] + bv.x, c[nt][3] + bv.y);
    }
}

// epilogue -> pre-split uint2 (kupz layout) (q, k)
__device__ __forceinline__
void mma_epi_pre(float c[4][4], const float* __restrict__ bias, int boff,
                 uint2* __restrict__ outU, int wp, int lane)
{
    const int rg = wp >> 2, cg = wp & 3;
    const int r = rg * 16 + (lane >> 2);
    const int q2 = (lane & 3) * 2;
    #pragma unroll
    for (int nt = 0; nt < 4; ++nt) {
        const int col = cg * 32 + nt * 8 + q2;
        const float2 bv = *(const float2*)(bias + boff + col);
        outU[kupz(r,     col >> 1)] = split_pair(c[nt][0] + bv.x, c[nt][1] + bv.y);
        outU[kupz(r + 8, col >> 1)] = split_pair(c[nt][2] + bv.x, c[nt][3] + bv.y);
    }
}

// ---------------- kernel 2 ----------------
__global__ __launch_bounds__(NTHR, 2)
void k_main(const float* __restrict__ rpp,
            const float* __restrict__ q_b, const float* __restrict__ kv_b,
            const float* __restrict__ o_b, float* __restrict__ out)
{
    extern __shared__ float sm[];
    float* bufA = sm;            // q uint2 -> attn-out uint2 (in-place per warp region)
    float* bufB = bufA + 8192;   // xd2 uint2 -> v f32 (in-place, barrier-protected)
    float* bufC = bufB + 8192;   // xd f32 -> k uint2

    uint2* AU = (uint2*)bufA;
    uint2* BU = (uint2*)bufB;
    uint2* CU = (uint2*)bufC;

    const int win = blockIdx.x;
    const int b   = win >> 10;
    const int wr  = win & 1023;
    const int wi  = wr >> 5;
    const int wj  = wr & 31;
    const int tid = threadIdx.x;
    const int wp  = tid >> 5, tx = tid & 31;

    // ---- inter-window bilinear blend -> bufC (xd f32) ----
    {
        const float ox = __ldg(g_oi + win * 2 + 0), oy = __ldg(g_oi + win * 2 + 1);
        const float gxp = (float)wj + ox, gyp = (float)wi + oy;
        const float x0f = floorf(gxp), y0f = floorf(gyp);
        const float fx = gxp - x0f, fy = gyp - y0f;
        const int x0 = (int)x0f, y0 = (int)y0f;
        const float wgt[4] = {(1.f - fx) * (1.f - fy), fx * (1.f - fy),
                              (1.f - fx) * fy,          fx * fy};
        const float4* nb[4];
        float nww[4];
        #pragma unroll
        for (int k = 0; k < 4; ++k) {
            const int xx = x0 + (k & 1), yy = y0 + (k >> 1);
            const bool valid = (xx >= 0) && (xx < W1G) && (yy >= 0) && (yy < W1G);
            nb[k]  = (const float4*)(valid ? (g_xw + (size_t)((b << 10) + (yy << 5) + xx) * P2 * CH)
                                           : g_xw);
            nww[k] = valid ? wgt[k] : 0.f;
        }
        float4* outv4 = (float4*)bufC;
        for (int i4 = tid; i4 < 2048; i4 += NTHR) {
            const float4 v0 = __ldg(nb[0] + i4), v1 = __ldg(nb[1] + i4);
            const float4 v2 = __ldg(nb[2] + i4), v3 = __ldg(nb[3] + i4);
            float4 r;
            r.x = nww[0]*v0.x + nww[1]*v1.x + nww[2]*v2.x + nww[3]*v3.x;
            r.y = nww[0]*v0.y + nww[1]*v1.y + nww[2]*v2.y + nww[3]*v3.y;
            r.z = nww[0]*v0.z + nww[1]*v1.z + nww[2]*v2.z + nww[3]*v3.z;
            r.w = nww[0]*v0.w + nww[1]*v1.w + nww[2]*v2.w + nww[3]*v3.w;
            outv4[swz4(i4 >> 5, i4 & 31)] = r;
        }
    }
    __syncthreads();

    // ---- intra-window gather bufC -> bufB (xd2, PRE-SPLIT uint2 kupz) ----
    {
        const float4* inv4 = (const float4*)bufC;
        #pragma unroll
        for (int it = 0; it < 4; ++it) {
            const int i4 = tid + it * NTHR;
            const int tok = i4 >> 5, c4 = i4 & 31;
            const int pi = tok >> 3, pj = tok & 7;
            const float o0 = __ldg(g_off + win * 128 + tok * 2);
            const float o1 = __ldg(g_off + win * 128 + tok * 2 + 1);
            const float gx2 = (float)pj + o0, gy2 = (float)pi + o1;
            const float xf = floorf(gx2), yf = floorf(gy2);
            const float fx = gx2 - xf, fy = gy2 - yf;
            const int x0 = (int)xf, y0 = (int)yf;
            const float ww[4] = {(1.f - fx) * (1.f - fy), fx * (1.f - fy),
                                 (1.f - fx) * fy,          fx * fy};
            float4 r = make_float4(0.f, 0.f, 0.f, 0.f);
            #pragma unroll
            for (int k = 0; k < 4; ++k) {
                const int xx = x0 + (k & 1), yy = y0 + (k >> 1);
                const bool valid = (xx >= 0) && (xx < WSZ) && (yy >= 0) && (yy < WSZ);
                const int idx = valid ? (yy * 8 + xx) : 0;
                const float wk = valid ? ww[k] : 0.f;
                const float4 a = inv4[swz4(idx, c4)];
                r.x = fmaf(wk, a.x, r.x);
                r.y = fmaf(wk, a.y, r.y);
                r.z = fmaf(wk, a.z, r.z);
                r.w = fmaf(wk, a.w, r.w);
            }
            const uint2 p0 = split_pair(r.x, r.y);
            const uint2 p1 = split_pair(r.z, r.w);
            // contiguous uint4 store at even slot (2c4 ^ f is even)
            *(uint4*)(BU + kupz(tok, 2 * c4)) = make_uint4(p0.x, p0.y, p1.x, p1.y);
        }
    }
    __syncthreads();

    // ---- GEMMs on tensor cores (all A operands pre-split; no mainloop splits) ----
    {   // k: BU(xd2) -> CU pre-split (xd dead)
        float c[4][4] = {};
        mma_main_pre(BU, g_kf, wp, tx, c);
        mma_epi_pre(c, kv_b, 0, CU, wp, tx);
    }
    {   // q: g_xq -> AU pre-split
        float c[4][4] = {};
        mma_main_preg(g_xq + (size_t)win * P2 * 64, g_qf, wp, tx, c);
        mma_epi_pre(c, q_b, 0, AU, wp, tx);
    }
    {   // v: BU -> bufB f32 in-place (barrier between reads and writes)
        float c[4][4] = {};
        mma_main_pre(BU, g_vf, wp, tx, c);
        __syncthreads();
        mma_epi_smem(c, kv_b, 128, bufB, wp, tx);
    }
    __syncthreads();

    // ---- attention, register-resident per warp (hh = wp&3, rg = wp>>2) ----
    {
        const float scale = 0.17677669529663687f;
        const bool lastRow = (wi == W1G - 1), lastCol = (wj == W1G - 1);
        const int hh = wp & 3, rg = wp >> 2;
        const int rA = rg * 16 + (tx >> 2);
        const int q2 = (tx & 3) * 2;
        const int la3 = tx & 3;

        // -- QK: A = AU (pre-split q), B = CU (pre-split k) --
        float c[8][4] = {};
        #pragma unroll
        for (int ks = 0; ks < 2; ++ks) {
            const int chp = hh * 16 + ks * 8 + la3;
            const uint2 a0 = AU[kupz(rA,     chp)];
            const uint2 a1 = AU[kupz(rA + 8, chp)];
            const uint2 a2 = AU[kupz(rA,     chp + 4)];
            const uint2 a3 = AU[kupz(rA + 8, chp + 4)];
            #pragma unroll
            for (int nt = 0; nt < 8; ++nt) {
                const int n = nt * 8 + (tx >> 2);
                const uint2 b0 = CU[kupz(n, chp)];
                const uint2 b1 = CU[kupz(n, chp + 4)];
                mma3u(c[nt], a0, a1, a2, a3, b0.x, b1.x, b0.y, b1.y);
            }
        }

        // -- bias + mask + scale (R15 style) --
        const float* rb = rpp + hh * 225;
        #pragma unroll
        for (int nt = 0; nt < 8; ++nt) {
            #pragma unroll
            for (int h2 = 0; h2 < 2; ++h2) {
                const int i = rA + 8 * h2;
                const int pi_i = i >> 3, pj_i = i & 7;
                #pragma unroll
                for (int u = 0; u < 2; ++u) {
                    const int j = nt * 8 + q2 + u;
                    const int pi_j = j >> 3, pj_j = j & 7;
                    const float bias = __ldg(rb + (pi_i - pi_j + 7) * 15 + (pj_i - pj_j + 7));
                    const bool msk = (lastRow && ((pi_i < 4) != (pi_j < 4)))
                                  || (lastCol && ((pj_i < 4) != (pj_j < 4)));
                    c[nt][2 * h2 + u] = msk ? -CUDART_INF_F
                                            : fmaf(c[nt][2 * h2 + u], scale, bias);
                }
            }
        }

        // -- softmax in registers --
        float m0 = -CUDART_INF_F, m1 = -CUDART_INF_F;
        #pragma unroll
        for (int nt = 0; nt < 8; ++nt) {
            m0 = fmaxf(m0, fmaxf(c[nt][0], c[nt][1]));
            m1 = fmaxf(m1, fmaxf(c[nt][2], c[nt][3]));
        }
        m0 = fmaxf(m0, __shfl_xor_sync(0xffffffffu, m0, 1));
        m0 = fmaxf(m0, __shfl_xor_sync(0xffffffffu, m0, 2));
        m1 = fmaxf(m1, __shfl_xor_sync(0xffffffffu, m1, 1));
        m1 = fmaxf(m1, __shfl_xor_sync(0xffffffffu, m1, 2));
        float s0 = 0.f, s1 = 0.f;
        #pragma unroll
        for (int nt = 0; nt < 8; ++nt) {
            c[nt][0] = __expf(c[nt][0] - m0);
            c[nt][1] = __expf(c[nt][1] - m0);
            c[nt][2] = __expf(c[nt][2] - m1);
            c[nt][3] = __expf(c[nt][3] - m1);
            s0 += c[nt][0] + c[nt][1];
            s1 += c[nt][2] + c[nt][3];
        }
        s0 += __shfl_xor_sync(0xffffffffu, s0, 1);
        s0 += __shfl_xor_sync(0xffffffffu, s0, 2);
        s1 += __shfl_xor_sync(0xffffffffu, s1, 1);
        s1 += __shfl_xor_sync(0xffffffffu, s1, 2);
        const float inv0 = 1.f / s0, inv1 = 1.f / s1;

        // -- pack probs -> PV A-fragments (C->A layout identity) --
        uint2 aF[4][4];
        #pragma unroll
        for (int ks = 0; ks < 4; ++ks) {
            aF[ks][0] = split_pair(c[2*ks][0]   * inv0, c[2*ks][1]   * inv0);
            aF[ks][1] = split_pair(c[2*ks][2]   * inv1, c[2*ks][3]   * inv1);
            aF[ks][2] = split_pair(c[2*ks+1][0] * inv0, c[2*ks+1][1] * inv0);
            aF[ks][3] = split_pair(c[2*ks+1][2] * inv1, c[2*ks+1][3] * inv1);
        }

        // -- PV: v f32 (split at use, R15 style); write attn-out PRE-SPLIT into AU --
        #pragma unroll
        for (int nt = 0; nt < 4; ++nt) {
            float c4[4] = {};
            const int nV = hh * HD + nt * 8 + (tx >> 2);
            #pragma unroll
            for (int ks = 0; ks < 4; ++ks) {
                const int k0 = ks * 16;
                const float v00 = bufB[swz(k0 + q2,     nV)];
                const float v01 = bufB[swz(k0 + q2 + 1, nV)];
                const float v10 = bufB[swz(k0 + q2 + 8, nV)];
                const float v11 = bufB[swz(k0 + q2 + 9, nV)];
                const unsigned bh0 = prmt_hi(v00, v01);
                const unsigned bl0 = pack_rn(v00 - trunc_hi(v00), v01 - trunc_hi(v01));
                const unsigned bh1 = prmt_hi(v10, v11);
                const unsigned bl1 = pack_rn(v10 - trunc_hi(v10), v11 - trunc_hi(v11));
                mma3u(c4, aF[ks][0], aF[ks][1], aF[ks][2], aF[ks][3], bh0, bh1, bl0, bl1);
            }
            const int pO = hh * 16 + nt * 4 + la3;
            AU[kupz(rA,     pO)] = split_pair(c4[0], c4[1]);
            AU[kupz(rA + 8, pO)] = split_pair(c4[2], c4[3]);
        }
    }
    __syncthreads();

    // ---- o projection (A = AU pre-split attn-out) + un-shift scatter ----
    {
        float c[4][4] = {};
        mma_main_pre(AU, g_of, wp, tx, c);
        const int rg = wp >> 2, cg = wp & 3;
        const int rA = rg * 16 + (tx >> 2);
        const int q2 = (tx & 3) * 2;
        #pragma unroll
        for (int nt = 0; nt < 4; ++nt) {
            const int col = cg * 32 + nt * 8 + q2;
            const float2 bv = *(const float2*)(o_b + col);
            #pragma unroll
            for (int h = 0; h < 2; ++h) {
                const int tok = rA + 8 * h;
                const int pi = tok >> 3, pj = tok & 7;
                const int rr = (wi * 8 + pi + SHIFT) & 255;
                const int cc = (wj * 8 + pj + SHIFT) & 255;
                float2 o;
                o.x = c[nt][2 * h + 0] + bv.x;
                o.y = c[nt][2 * h + 1] + bv.y;
                *(float2*)(out + (size_t)((((b << 8) + rr) << 8) + cc) * CH + col) = o;
            }
        }
    }
}

extern "C" void kernel_launch(void* const* d_in, const int* in_sizes, int n_in,
                              void* d_out, int out_size)
{
    const float* x    = (const float*)d_in[0];
    const float* rpp  = (const float*)d_in[1];
    const float* wi_w = (const float*)d_in[2];
    const float* wi_b = (const float*)d_in[3];
    const float* w1_w = (const float*)d_in[4];
    const float* w1_b = (const float*)d_in[5];
    const float* w2_w = (const float*)d_in[6];
    const float* w2_b = (const float*)d_in[7];
    const float* q_w  = (const float*)d_in[8];
    const float* q_b  = (const float*)d_in[9];
    const float* kv_w = (const float*)d_in[10];
    const float* kv_b = (const float*)d_in[11];
    const float* o_w  = (const float*)d_in[12];
    const float* o_b  = (const float*)d_in[13];
    float* out = (float*)d_out;

    const size_t smem2 = (size_t)(3 * 8192) * sizeof(float);   // 96 KB -> 2 CTAs/SM
    cudaFuncSetAttribute(k_main, cudaFuncAttributeMaxDynamicSharedMemorySize, (int)smem2);

    k_wfrag<<<16, 256>>>(q_w, kv_w, o_w);
    k_prep<<<NWIN, 256>>>(x, wi_w, wi_b, w1_w, w1_b, w2_w, w2_b);
    k_main<<<NWIN, NTHR, smem2>>>(rpp, q_b, kv_b, o_b, out);
}